// round 3
// baseline (speedup 1.0000x reference)
#include <cuda_runtime.h>
#include <math.h>

#define NB 32
#define NK 4
#define NC 256
#define HW 1024
#define MID 32
#define KC 1280   // (K+1)*C
#define EPSV 1e-5f

// Scratch (device globals — no allocation allowed)
__device__ float g_feats[NB * KC];       // [B, 5*C] pooled features
__device__ float g_w1[NB * NC];          // sigmoid self-gate
__device__ float g_w2[NB * NK * NC];     // softmax branch gates

// ---------------------------------------------------------------------------
// Kernel 1: global-average-pool means for all 5 tensors.
// One warp per (tensor, b, c) row of 1024 contiguous floats.
// 40960 rows total -> 5120 blocks x 256 threads (8 warps).
// ---------------------------------------------------------------------------
__global__ __launch_bounds__(256) void means_kernel(
    const float* __restrict__ y,
    const float* __restrict__ x0,
    const float* __restrict__ x1,
    const float* __restrict__ x2,
    const float* __restrict__ x3)
{
    int warp = threadIdx.x >> 5;
    int lane = threadIdx.x & 31;
    int r = blockIdx.x * 8 + warp;          // 0 .. 40959
    int t = r >> 13;                        // tensor id 0..4 (8192 rows each)
    int rem = r & 8191;                     // b*256 + c

    const float* src = (t == 0) ? y : (t == 1) ? x0 : (t == 2) ? x1
                     : (t == 3) ? x2 : x3;
    const float4* p = (const float4*)(src + (size_t)rem * HW);

    float s = 0.f;
#pragma unroll
    for (int i = 0; i < 8; i++) {
        float4 v = p[lane + i * 32];
        s += (v.x + v.y) + (v.z + v.w);
    }
#pragma unroll
    for (int o = 16; o; o >>= 1) s += __shfl_xor_sync(0xFFFFFFFFu, s, o);

    if (lane == 0) {
        int b = rem >> 8, c = rem & 255;
        g_feats[b * KC + t * NC + c] = s * (1.0f / 1024.0f);
    }
}

// ---------------------------------------------------------------------------
// Kernel 2: feats @ conv1_w.T -> BN -> ReLU -> @ conv2_w.T + b -> gates.
// Single block of 1024 threads; total FLOPs trivial (~5 MFLOP).
// ---------------------------------------------------------------------------
__global__ __launch_bounds__(1024) void gemm_gates_kernel(
    const float* __restrict__ conv1_w,   // [MID, KC]
    const float* __restrict__ bn_gamma,
    const float* __restrict__ bn_beta,
    const float* __restrict__ bn_mean,
    const float* __restrict__ bn_var,
    const float* __restrict__ conv2_w,   // [KC, MID]
    const float* __restrict__ conv2_b)   // [KC]
{
    __shared__ float h_s[NB][MID + 1];
    int tid = threadIdx.x;

    // Stage A: h[b][m] = relu(BN(dot(feats[b,:], conv1_w[m,:])))
    {
        int b = tid >> 5;
        int m = tid & 31;
        const float* f = g_feats + b * KC;
        const float* w = conv1_w + m * KC;
        float acc = 0.f;
#pragma unroll 4
        for (int k = 0; k < KC; k += 4) {
            acc = fmaf(f[k], w[k], acc);
            acc = fmaf(f[k + 1], w[k + 1], acc);
            acc = fmaf(f[k + 2], w[k + 2], acc);
            acc = fmaf(f[k + 3], w[k + 3], acc);
        }
        float inv = rsqrtf(bn_var[m] + EPSV);
        float hv = (acc - bn_mean[m]) * (bn_gamma[m] * inv) + bn_beta[m];
        h_s[b][m] = fmaxf(hv, 0.f);
    }
    __syncthreads();

    // Stage B: per (b,c) compute 5 logits, then sigmoid + softmax-over-K.
    // 8192 (b,c) pairs -> 8 per thread.
#pragma unroll
    for (int i = 0; i < 8; i++) {
        int p = tid + i * 1024;
        int b = p >> 8, c = p & 255;
        float wv[5];
#pragma unroll
        for (int s = 0; s < 5; s++) {
            int j = s * NC + c;
            const float* w2r = conv2_w + j * MID;
            float acc = conv2_b[j];
#pragma unroll
            for (int m = 0; m < MID; m++) acc = fmaf(h_s[b][m], w2r[m], acc);
            wv[s] = acc;
        }
        // self gate
        g_w1[b * NC + c] = 1.0f / (1.0f + expf(-wv[0]));
        // softmax over k=1..4
        float mx = fmaxf(fmaxf(wv[1], wv[2]), fmaxf(wv[3], wv[4]));
        float e0 = expf(wv[1] - mx);
        float e1 = expf(wv[2] - mx);
        float e2 = expf(wv[3] - mx);
        float e3 = expf(wv[4] - mx);
        float inv = 1.0f / (e0 + e1 + e2 + e3);
        g_w2[(b * NK + 0) * NC + c] = e0 * inv;
        g_w2[(b * NK + 1) * NC + c] = e1 * inv;
        g_w2[(b * NK + 2) * NC + c] = e2 * inv;
        g_w2[(b * NK + 3) * NC + c] = e3 * inv;
    }
}

// ---------------------------------------------------------------------------
// Kernel 3: out[b,c,:] = y*w1 + sum_k w2[k]*x_k. One block per (b,c) row,
// 256 threads, one float4 per thread. Fully coalesced 128B/warp accesses.
// ---------------------------------------------------------------------------
__global__ __launch_bounds__(256) void gated_out_kernel(
    const float* __restrict__ y,
    const float* __restrict__ x0,
    const float* __restrict__ x1,
    const float* __restrict__ x2,
    const float* __restrict__ x3,
    float* __restrict__ out)
{
    int bc = blockIdx.x;                 // 0 .. 8191 = b*256 + c
    int b = bc >> 8, c = bc & 255;

    float w1 = g_w1[bc];
    float wa = g_w2[(b * NK + 0) * NC + c];
    float wb = g_w2[(b * NK + 1) * NC + c];
    float wc = g_w2[(b * NK + 2) * NC + c];
    float wd = g_w2[(b * NK + 3) * NC + c];

    size_t base = (size_t)bc * HW;
    const float4* y4 = (const float4*)(y + base);
    const float4* a4 = (const float4*)(x0 + base);
    const float4* b4 = (const float4*)(x1 + base);
    const float4* c4 = (const float4*)(x2 + base);
    const float4* d4 = (const float4*)(x3 + base);
    float4* o4 = (float4*)(out + base);

    int i = threadIdx.x;                 // 0..255 covers 1024 floats
    float4 vy = y4[i], va = a4[i], vb = b4[i], vc = c4[i], vd = d4[i];
    float4 r;
    r.x = fmaf(vy.x, w1, fmaf(va.x, wa, fmaf(vb.x, wb, fmaf(vc.x, wc, vd.x * wd))));
    r.y = fmaf(vy.y, w1, fmaf(va.y, wa, fmaf(vb.y, wb, fmaf(vc.y, wc, vd.y * wd))));
    r.z = fmaf(vy.z, w1, fmaf(va.z, wa, fmaf(vb.z, wb, fmaf(vc.z, wc, vd.z * wd))));
    r.w = fmaf(vy.w, w1, fmaf(va.w, wa, fmaf(vb.w, wb, fmaf(vc.w, wc, vd.w * wd))));
    o4[i] = r;
}

extern "C" void kernel_launch(void* const* d_in, const int* in_sizes, int n_in,
                              void* d_out, int out_size)
{
    const float* y       = (const float*)d_in[0];
    const float* x0      = (const float*)d_in[1];
    const float* x1      = (const float*)d_in[2];
    const float* x2      = (const float*)d_in[3];
    const float* x3      = (const float*)d_in[4];
    const float* conv1_w = (const float*)d_in[5];
    const float* bn_g    = (const float*)d_in[6];
    const float* bn_b    = (const float*)d_in[7];
    const float* bn_m    = (const float*)d_in[8];
    const float* bn_v    = (const float*)d_in[9];
    const float* conv2_w = (const float*)d_in[10];
    const float* conv2_b = (const float*)d_in[11];
    float* out = (float*)d_out;

    means_kernel<<<5120, 256>>>(y, x0, x1, x2, x3);
    gemm_gates_kernel<<<1, 1024>>>(conv1_w, bn_g, bn_b, bn_m, bn_v,
                                   conv2_w, conv2_b);
    gated_out_kernel<<<8192, 256>>>(y, x0, x1, x2, x3, out);
}

// round 4
// speedup vs baseline: 14.5222x; 14.5222x over previous
#include <cuda_runtime.h>
#include <math.h>

#define NB 32
#define NK 4
#define NC 256
#define HW 1024
#define MID 32
#define KC 1280   // (K+1)*C
#define EPSV 1e-5f

// Scratch (device globals — no allocation allowed)
__device__ float g_feats[NB * KC];       // [B, 5*C] pooled features
__device__ float g_w1[NB * NC];          // sigmoid self-gate
__device__ float g_w2[NB * NK * NC];     // softmax branch gates

// ---------------------------------------------------------------------------
// Kernel 1: global-average-pool means for all 5 tensors.
// One warp per (tensor, b, c) row of 1024 contiguous floats.
// 40960 rows total -> 5120 blocks x 256 threads (8 warps).
// Measured: 27.7us @ 78% DRAM — at roofline, unchanged.
// ---------------------------------------------------------------------------
__global__ __launch_bounds__(256) void means_kernel(
    const float* __restrict__ y,
    const float* __restrict__ x0,
    const float* __restrict__ x1,
    const float* __restrict__ x2,
    const float* __restrict__ x3)
{
    int warp = threadIdx.x >> 5;
    int lane = threadIdx.x & 31;
    int r = blockIdx.x * 8 + warp;          // 0 .. 40959
    int t = r >> 13;                        // tensor id 0..4 (8192 rows each)
    int rem = r & 8191;                     // b*256 + c

    const float* src = (t == 0) ? y : (t == 1) ? x0 : (t == 2) ? x1
                     : (t == 3) ? x2 : x3;
    const float4* p = (const float4*)(src + (size_t)rem * HW);

    float s = 0.f;
#pragma unroll
    for (int i = 0; i < 8; i++) {
        float4 v = p[lane + i * 32];
        s += (v.x + v.y) + (v.z + v.w);
    }
#pragma unroll
    for (int o = 16; o; o >>= 1) s += __shfl_xor_sync(0xFFFFFFFFu, s, o);

    if (lane == 0) {
        int b = rem >> 8, c = rem & 255;
        g_feats[b * KC + t * NC + c] = s * (1.0f / 1024.0f);
    }
}

// ---------------------------------------------------------------------------
// Kernel 2: per-batch gate computation. Grid = 32 blocks (one per b).
// Stage A: 8 warps x 4 outputs -> h[b][m] = relu(BN(feats[b,:] . conv1_w[m,:]))
//          coalesced float4 lane-strided loads, shuffle reduce.
// Stage B: 256 threads (one per c): 5 dots of length 32 against conv2_w,
//          then sigmoid self-gate + softmax-over-K branch gates.
// ---------------------------------------------------------------------------
__global__ __launch_bounds__(256) void gates_kernel(
    const float* __restrict__ conv1_w,   // [MID, KC]
    const float* __restrict__ bn_gamma,
    const float* __restrict__ bn_beta,
    const float* __restrict__ bn_mean,
    const float* __restrict__ bn_var,
    const float* __restrict__ conv2_w,   // [KC, MID]
    const float* __restrict__ conv2_b)   // [KC]
{
    __shared__ float h_s[MID];
    int b = blockIdx.x;
    int tid = threadIdx.x;
    int warp = tid >> 5;
    int lane = tid & 31;

    // Stage A: each warp computes 4 of the 32 hidden units.
    const float4* f4 = (const float4*)(g_feats + b * KC);  // 320 float4
#pragma unroll
    for (int mi = 0; mi < 4; mi++) {
        int m = warp * 4 + mi;
        const float4* w4 = (const float4*)(conv1_w + m * KC);
        float acc = 0.f;
#pragma unroll
        for (int i = 0; i < 10; i++) {                     // 320/32 = 10
            float4 fv = f4[lane + i * 32];
            float4 wv = w4[lane + i * 32];
            acc += fv.x * wv.x + fv.y * wv.y + fv.z * wv.z + fv.w * wv.w;
        }
#pragma unroll
        for (int o = 16; o; o >>= 1) acc += __shfl_xor_sync(0xFFFFFFFFu, acc, o);
        if (lane == 0) {
            float inv = rsqrtf(bn_var[m] + EPSV);
            float hv = (acc - bn_mean[m]) * (bn_gamma[m] * inv) + bn_beta[m];
            h_s[m] = fmaxf(hv, 0.f);
        }
    }
    __syncthreads();

    // Stage B: one thread per channel c.
    int c = tid;
    float h[MID];
#pragma unroll
    for (int m = 0; m < MID; m++) h[m] = h_s[m];

    float wv[5];
#pragma unroll
    for (int s = 0; s < 5; s++) {
        int j = s * NC + c;
        const float4* w2r = (const float4*)(conv2_w + j * MID);
        float acc = conv2_b[j];
#pragma unroll
        for (int q = 0; q < 8; q++) {
            float4 v = w2r[q];
            acc = fmaf(h[q * 4 + 0], v.x, acc);
            acc = fmaf(h[q * 4 + 1], v.y, acc);
            acc = fmaf(h[q * 4 + 2], v.z, acc);
            acc = fmaf(h[q * 4 + 3], v.w, acc);
        }
        wv[s] = acc;
    }

    g_w1[b * NC + c] = 1.0f / (1.0f + expf(-wv[0]));

    float mx = fmaxf(fmaxf(wv[1], wv[2]), fmaxf(wv[3], wv[4]));
    float e0 = expf(wv[1] - mx);
    float e1 = expf(wv[2] - mx);
    float e2 = expf(wv[3] - mx);
    float e3 = expf(wv[4] - mx);
    float inv = 1.0f / (e0 + e1 + e2 + e3);
    g_w2[(b * NK + 0) * NC + c] = e0 * inv;
    g_w2[(b * NK + 1) * NC + c] = e1 * inv;
    g_w2[(b * NK + 2) * NC + c] = e2 * inv;
    g_w2[(b * NK + 3) * NC + c] = e3 * inv;
}

// ---------------------------------------------------------------------------
// Kernel 3: out[b,c,:] = y*w1 + sum_k w2[k]*x_k. One block per (b,c) row,
// 256 threads, one float4 per thread. Fully coalesced 128B/warp accesses.
// ---------------------------------------------------------------------------
__global__ __launch_bounds__(256) void gated_out_kernel(
    const float* __restrict__ y,
    const float* __restrict__ x0,
    const float* __restrict__ x1,
    const float* __restrict__ x2,
    const float* __restrict__ x3,
    float* __restrict__ out)
{
    int bc = blockIdx.x;                 // 0 .. 8191 = b*256 + c
    int b = bc >> 8, c = bc & 255;

    float w1 = g_w1[bc];
    float wa = g_w2[(b * NK + 0) * NC + c];
    float wb = g_w2[(b * NK + 1) * NC + c];
    float wc = g_w2[(b * NK + 2) * NC + c];
    float wd = g_w2[(b * NK + 3) * NC + c];

    size_t base = (size_t)bc * HW;
    const float4* y4 = (const float4*)(y + base);
    const float4* a4 = (const float4*)(x0 + base);
    const float4* b4 = (const float4*)(x1 + base);
    const float4* c4 = (const float4*)(x2 + base);
    const float4* d4 = (const float4*)(x3 + base);
    float4* o4 = (float4*)(out + base);

    int i = threadIdx.x;                 // 0..255 covers 1024 floats
    float4 vy = y4[i], va = a4[i], vb = b4[i], vc = c4[i], vd = d4[i];
    float4 r;
    r.x = fmaf(vy.x, w1, fmaf(va.x, wa, fmaf(vb.x, wb, fmaf(vc.x, wc, vd.x * wd))));
    r.y = fmaf(vy.y, w1, fmaf(va.y, wa, fmaf(vb.y, wb, fmaf(vc.y, wc, vd.y * wd))));
    r.z = fmaf(vy.z, w1, fmaf(va.z, wa, fmaf(vb.z, wb, fmaf(vc.z, wc, vd.z * wd))));
    r.w = fmaf(vy.w, w1, fmaf(va.w, wa, fmaf(vb.w, wb, fmaf(vc.w, wc, vd.w * wd))));
    o4[i] = r;
}

extern "C" void kernel_launch(void* const* d_in, const int* in_sizes, int n_in,
                              void* d_out, int out_size)
{
    const float* y       = (const float*)d_in[0];
    const float* x0      = (const float*)d_in[1];
    const float* x1      = (const float*)d_in[2];
    const float* x2      = (const float*)d_in[3];
    const float* x3      = (const float*)d_in[4];
    const float* conv1_w = (const float*)d_in[5];
    const float* bn_g    = (const float*)d_in[6];
    const float* bn_b    = (const float*)d_in[7];
    const float* bn_m    = (const float*)d_in[8];
    const float* bn_v    = (const float*)d_in[9];
    const float* conv2_w = (const float*)d_in[10];
    const float* conv2_b = (const float*)d_in[11];
    float* out = (float*)d_out;

    means_kernel<<<5120, 256>>>(y, x0, x1, x2, x3);
    gates_kernel<<<NB, 256>>>(conv1_w, bn_g, bn_b, bn_m, bn_v,
                              conv2_w, conv2_b);
    gated_out_kernel<<<8192, 256>>>(y, x0, x1, x2, x3, out);
}

// round 8
// speedup vs baseline: 18.7945x; 1.2942x over previous
#include <cuda_runtime.h>
#include <math.h>

#define NB 32
#define NK 4
#define NC 256
#define HW 1024
#define MID 32
#define KC 1280   // (K+1)*C
#define EPSV 1e-5f

#define NBLK 128        // 8192 bc rows / 64 per block; all resident (<=148 SMs)
#define BC_PER_BLK 64

// Scratch (device globals — no allocation allowed). Zero-initialized once;
// barrier counters are returned to 0 by the kernel itself (graph-replay safe).
__device__ float g_feats[NB * KC];
__device__ unsigned g_cnt1;
__device__ unsigned g_cnt2;

// ---------------------------------------------------------------------------
// Single fused persistent kernel:
//   Phase 1: global-average-pool means for this block's 64 (b,c) rows x 5 tensors.
//   Grid barrier (self-resetting counters).
//   Gates:   h[b][:] + sigmoid/softmax gates for this block's rows (redundant
//            per-b work across the 4 blocks sharing b — trivial FLOPs).
//   Phase 2: gated sum, re-reading the slice in REVERSE order so the tail of
//            phase 1's stream (still L2-resident) hits in L2. Output stored
//            with .cs (evict-first) to avoid polluting L2.
// ---------------------------------------------------------------------------
__global__ __launch_bounds__(1024, 1) void fused_kernel(
    const float* __restrict__ y,
    const float* __restrict__ x0,
    const float* __restrict__ x1,
    const float* __restrict__ x2,
    const float* __restrict__ x3,
    const float* __restrict__ conv1_w,   // [MID, KC]
    const float* __restrict__ bn_gamma,
    const float* __restrict__ bn_beta,
    const float* __restrict__ bn_mean,
    const float* __restrict__ bn_var,
    const float* __restrict__ conv2_w,   // [KC, MID]
    const float* __restrict__ conv2_b,   // [KC]
    float* __restrict__ out)
{
    __shared__ float h_s[MID];
    __shared__ float sw1[BC_PER_BLK];
    __shared__ float sw2[NK][BC_PER_BLK];

    const int tid  = threadIdx.x;
    const int warp = tid >> 5;
    const int lane = tid & 31;
    const int s    = blockIdx.x * BC_PER_BLK;   // first bc row of this block
    const int b    = s >> 8;                    // 64 | 256 -> single b per block

    // ---------------- Phase 1: means (warp per row) ----------------
    // 64 bc * 5 tensors = 320 row-tasks over 32 warps -> 10 iters.
#pragma unroll
    for (int it = 0; it < 10; it++) {
        int task = warp + it * 32;              // 0..319
        int bc   = s + (task / 5);
        int t    = task % 5;
        const float* src = (t == 0) ? y : (t == 1) ? x0 : (t == 2) ? x1
                         : (t == 3) ? x2 : x3;
        const float4* p = (const float4*)(src + (size_t)bc * HW);
        float sum = 0.f;
#pragma unroll
        for (int i = 0; i < 8; i++) {
            float4 v = p[lane + i * 32];
            sum += (v.x + v.y) + (v.z + v.w);
        }
#pragma unroll
        for (int o = 16; o; o >>= 1) sum += __shfl_xor_sync(0xFFFFFFFFu, sum, o);
        if (lane == 0) {
            int c = bc & 255;
            g_feats[b * KC + t * NC + c] = sum * (1.0f / 1024.0f);
        }
    }

    // ---------------- Grid barrier (self-resetting, replay-safe) ----------
    __threadfence();
    __syncthreads();
    if (tid == 0) {
        atomicAdd(&g_cnt1, 1u);
        while (*((volatile unsigned*)&g_cnt1) < (unsigned)NBLK) { }
        __threadfence();
        unsigned old = atomicAdd(&g_cnt2, 1u);
        if (old == (unsigned)(NBLK - 1)) {   // all blocks passed the spin
            g_cnt1 = 0u;
            __threadfence();
            g_cnt2 = 0u;
        }
    }
    __syncthreads();

    // ---------------- Gates: h[b][:] then per-channel gates ----------------
    // Warp m computes h[m] = relu(BN(feats[b,:] . conv1_w[m,:])).
    {
        int m = warp;
        const float4* f4 = (const float4*)(g_feats + b * KC);   // 320 float4
        const float4* w4 = (const float4*)(conv1_w + m * KC);
        float acc = 0.f;
#pragma unroll
        for (int i = 0; i < 10; i++) {
            float4 fv = f4[lane + i * 32];
            float4 wv = w4[lane + i * 32];
            acc += fv.x * wv.x + fv.y * wv.y + fv.z * wv.z + fv.w * wv.w;
        }
#pragma unroll
        for (int o = 16; o; o >>= 1) acc += __shfl_xor_sync(0xFFFFFFFFu, acc, o);
        if (lane == 0) {
            float inv = rsqrtf(bn_var[m] + EPSV);
            float hv  = (acc - bn_mean[m]) * (bn_gamma[m] * inv) + bn_beta[m];
            h_s[m] = fmaxf(hv, 0.f);
        }
    }
    __syncthreads();

    if (tid < BC_PER_BLK) {
        int bc = s + tid;
        int c  = bc & 255;
        float h[MID];
#pragma unroll
        for (int m = 0; m < MID; m++) h[m] = h_s[m];

        float wv[5];
#pragma unroll
        for (int t = 0; t < 5; t++) {
            int j = t * NC + c;
            const float4* w2r = (const float4*)(conv2_w + j * MID);
            float acc = conv2_b[j];
#pragma unroll
            for (int q = 0; q < 8; q++) {
                float4 v = w2r[q];
                acc = fmaf(h[q * 4 + 0], v.x, acc);
                acc = fmaf(h[q * 4 + 1], v.y, acc);
                acc = fmaf(h[q * 4 + 2], v.z, acc);
                acc = fmaf(h[q * 4 + 3], v.w, acc);
            }
            wv[t] = acc;
        }

        sw1[tid] = 1.0f / (1.0f + expf(-wv[0]));
        float mx = fmaxf(fmaxf(wv[1], wv[2]), fmaxf(wv[3], wv[4]));
        float e0 = expf(wv[1] - mx);
        float e1 = expf(wv[2] - mx);
        float e2 = expf(wv[3] - mx);
        float e3 = expf(wv[4] - mx);
        float inv = 1.0f / (e0 + e1 + e2 + e3);
        sw2[0][tid] = e0 * inv;
        sw2[1][tid] = e1 * inv;
        sw2[2][tid] = e2 * inv;
        sw2[3][tid] = e3 * inv;
    }
    __syncthreads();

    // ---------------- Phase 2: gated sum, REVERSE order for L2 hits --------
    // 1024 threads = 4 row-groups of 256; group g handles bc = s + it*4 + g.
    {
        const int g = tid >> 8;          // 0..3
        const int r = tid & 255;         // float4 index within the 1024-row
#pragma unroll
        for (int it = (BC_PER_BLK / 4) - 1; it >= 0; it--) {
            int rel = it * 4 + g;
            int bc  = s + rel;
            size_t base = (size_t)bc * HW;
            const float4* y4 = (const float4*)(y  + base);
            const float4* a4 = (const float4*)(x0 + base);
            const float4* b4 = (const float4*)(x1 + base);
            const float4* c4 = (const float4*)(x2 + base);
            const float4* d4 = (const float4*)(x3 + base);

            float w1 = sw1[rel];
            float wa = sw2[0][rel];
            float wb = sw2[1][rel];
            float wc = sw2[2][rel];
            float wd = sw2[3][rel];

            float4 vy = y4[r], va = a4[r], vb = b4[r], vc = c4[r], vd = d4[r];
            float4 res;
            res.x = fmaf(vy.x, w1, fmaf(va.x, wa, fmaf(vb.x, wb, fmaf(vc.x, wc, vd.x * wd))));
            res.y = fmaf(vy.y, w1, fmaf(va.y, wa, fmaf(vb.y, wb, fmaf(vc.y, wc, vd.y * wd))));
            res.z = fmaf(vy.z, w1, fmaf(va.z, wa, fmaf(vb.z, wb, fmaf(vc.z, wc, vd.z * wd))));
            res.w = fmaf(vy.w, w1, fmaf(va.w, wa, fmaf(vb.w, wb, fmaf(vc.w, wc, vd.w * wd))));
            __stcs((float4*)(out + base) + r, res);   // evict-first store
        }
    }
}

extern "C" void kernel_launch(void* const* d_in, const int* in_sizes, int n_in,
                              void* d_out, int out_size)
{
    const float* y       = (const float*)d_in[0];
    const float* x0      = (const float*)d_in[1];
    const float* x1      = (const float*)d_in[2];
    const float* x2      = (const float*)d_in[3];
    const float* x3      = (const float*)d_in[4];
    const float* conv1_w = (const float*)d_in[5];
    const float* bn_g    = (const float*)d_in[6];
    const float* bn_b    = (const float*)d_in[7];
    const float* bn_m    = (const float*)d_in[8];
    const float* bn_v    = (const float*)d_in[9];
    const float* conv2_w = (const float*)d_in[10];
    const float* conv2_b = (const float*)d_in[11];
    float* out = (float*)d_out;

    fused_kernel<<<NBLK, 1024>>>(y, x0, x1, x2, x3,
                                 conv1_w, bn_g, bn_b, bn_m, bn_v,
                                 conv2_w, conv2_b, out);
}